// round 14
// baseline (speedup 1.0000x reference)
#include <cuda_runtime.h>
#include <math.h>

// Problem dims
#define T_STEPS 1024
#define D_DIM   2048
#define NHID    2048
#define NCATS   1000

// Recurrence config: 148 persistent blocks, 28 warps (896 thr).
// Row-pair p in [0,7): rows b*14+2p, b*14+2p+1. Warps 4p+q (q=0..3) each
// compute the pair's 4 dots over K-quarter q; partials combined in SMEM.
#define GBLK    148
#define WARPS   28
#define RTPB    896
#define RPB     14
#define HBUF    4          // hp ring buffers (for 1-barrier-per-2-steps)

// ---------------- device scratch (no allocations allowed) ----------------
__device__ float    g_xz[T_STEPS * NHID];   // x @ Wz.T
__device__ float    g_xh[T_STEPS * NHID];   // x @ Wh.T
__device__ float    g_hp[HBUF][NHID];       // hp ring
__device__ float    g_logits[NCATS];
// Barrier state (R11-proven): 4 group counters on distinct L2 lines, root,
// single epoch word.
__device__ unsigned g_cnt4[128];
__device__ unsigned g_rootpad[32];
__device__ unsigned g_epochpad[32];

// ---------------- grid barrier (identical to R11/R13 passing version) -----
__device__ __forceinline__ void gbar(unsigned target, int bid) {
    __syncthreads();
    if (threadIdx.x == 0) {
        __threadfence();
        unsigned old = atomicAdd(&g_cnt4[(bid & 3) * 32], 1u);
        if (old % 37u == 36u) {                       // last arrival in group
            unsigned r = atomicAdd(&g_rootpad[0], 1u);
            if ((r & 3u) == 3u)                       // last group
                atomicExch(&g_epochpad[0], target);
        }
        while ((int)(*(volatile unsigned*)&g_epochpad[0] - target) < 0) {
            __nanosleep(32);
        }
        __threadfence();
    }
    __syncthreads();
}

__device__ __forceinline__ void st_cg(float* p, float v) {
    asm volatile("st.global.cg.f32 [%0], %1;" :: "l"(p), "f"(v) : "memory");
}

// ---------------- fused input projections (unchanged, proven) ------------
#define BM 128
#define BN 128
#define BK 16

__global__ __launch_bounds__(256, 2)
void gemm_xw_kernel(const float* __restrict__ x,
                    const float* __restrict__ Wz,
                    const float* __restrict__ Wh) {
    const float* W = (blockIdx.z == 0) ? Wz : Wh;
    float* C       = (blockIdx.z == 0) ? g_xz : g_xh;

    __shared__ float As[BK][BM];
    __shared__ float Bs[BK][BN];

    const int tid = threadIdx.x;
    const int m0  = blockIdx.y * BM;
    const int n0  = blockIdx.x * BN;
    const int tr  = tid >> 4;
    const int tc  = tid & 15;

    float acc[8][8];
#pragma unroll
    for (int i = 0; i < 8; i++)
#pragma unroll
        for (int j = 0; j < 8; j++) acc[i][j] = 0.0f;

    for (int k0 = 0; k0 < D_DIM; k0 += BK) {
#pragma unroll
        for (int r = 0; r < 2; r++) {
            int idx = tid + r * 256;
            int row = idx >> 2;
            int c4  = (idx & 3) << 2;
            float4 a = *(const float4*)(x + (size_t)(m0 + row) * D_DIM + k0 + c4);
            As[c4 + 0][row] = a.x; As[c4 + 1][row] = a.y;
            As[c4 + 2][row] = a.z; As[c4 + 3][row] = a.w;
            float4 b = *(const float4*)(W + (size_t)(n0 + row) * D_DIM + k0 + c4);
            Bs[c4 + 0][row] = b.x; Bs[c4 + 1][row] = b.y;
            Bs[c4 + 2][row] = b.z; Bs[c4 + 3][row] = b.w;
        }
        __syncthreads();
#pragma unroll
        for (int kk = 0; kk < BK; kk++) {
            float ra[8], rb[8];
            *(float4*)&ra[0] = *(const float4*)&As[kk][tr * 4];
            *(float4*)&ra[4] = *(const float4*)&As[kk][64 + tr * 4];
            *(float4*)&rb[0] = *(const float4*)&Bs[kk][tc * 4];
            *(float4*)&rb[4] = *(const float4*)&Bs[kk][64 + tc * 4];
#pragma unroll
            for (int i = 0; i < 8; i++)
#pragma unroll
                for (int j = 0; j < 8; j++)
                    acc[i][j] = fmaf(ra[i], rb[j], acc[i][j]);
        }
        __syncthreads();
    }

#pragma unroll
    for (int hi = 0; hi < 2; hi++)
#pragma unroll
        for (int i = 0; i < 4; i++) {
            int row = m0 + hi * 64 + tr * 4 + i;
#pragma unroll
            for (int hj = 0; hj < 2; hj++) {
                float4 v;
                v.x = acc[hi * 4 + i][hj * 4 + 0];
                v.y = acc[hi * 4 + i][hj * 4 + 1];
                v.z = acc[hi * 4 + i][hj * 4 + 2];
                v.w = acc[hi * 4 + i][hj * 4 + 3];
                *(float4*)(C + (size_t)row * NHID + n0 + hj * 64 + tc * 4) = v;
            }
        }
}

// ---------------- persistent recurrence + classifier + softmax ------------
// SMEM U layout (float4 units): warp w gets 512 float4 = 4 vectors x 128:
//   m=0: Uz[rp0], m=1: Uh[rp0], m=2: Uz[rp1], m=3: Uh[rp1],
//   each holding K-quarter q = w&3 (elements [q*512, q*512+512)).
__global__ __launch_bounds__(RTPB, 1)
void recur_kernel(const float* __restrict__ Uz,
                  const float* __restrict__ Uh,
                  const float* __restrict__ bz,
                  const float* __restrict__ zt0,
                  const float* __restrict__ htilde0,
                  const float* __restrict__ hprev0,
                  const float* __restrict__ Wout,
                  float* __restrict__ out) {
    extern __shared__ float sU[];        // 28 * 2048 floats = 229376 B
    __shared__ float sred4[2][WARPS][4]; // partial-dot exchange, double-buffered
    __shared__ float sredW[WARPS];       // softmax scratch

    const int b   = blockIdx.x;
    const int tid = threadIdx.x;
    const int w   = tid >> 5;
    const int l   = tid & 31;
    const int p   = w >> 2;              // pair index 0..6
    const int q   = w & 3;               // K-quarter
    const int r0  = b * RPB + 2 * p;     // pair's first row

    // Epoch base: read before this block's first arrival (proven pattern).
    unsigned e0 = *(volatile unsigned*)&g_epochpad[0];
    unsigned ec = 0;

    // one-time: load U slices into SMEM. 112 segments of 128 float4 each.
    for (int idx = tid; idx < WARPS * 4 * 128; idx += RTPB) {
        int seg = idx >> 7;              // 0..111
        int off = idx & 127;
        int wp  = seg >> 2;              // dest warp 0..27
        int m   = seg & 3;
        int pp  = wp >> 2, qq = wp & 3;
        int r   = b * RPB + 2 * pp + (m >> 1);
        if (r < NHID) {
            const float* src = ((m & 1) ? Uh : Uz) + (size_t)r * NHID + qq * 512;
            ((float4*)sU)[wp * 512 + m * 128 + off] = *(const float4*)(src + off * 4);
        }
    }

    // Owner state: q==0 warps, lanes 0/1 own rows r0, r0+1.
    int  myrow = r0 + l;
    bool owner = (q == 0) && (l < 2) && (myrow < NHID);
    float z_s = 0.f, ht_s = 0.f, h_s = 0.f, bzr = 0.f;
    if (owner) {
        z_s  = zt0[myrow];
        ht_s = htilde0[myrow];
        h_s  = hprev0[myrow];
        bzr  = bz[myrow];
        g_hp[0][myrow] = h_s;            // hp_0 = hprev0
    }
    gbar(e0 + (++ec), b);

    const float4* uw = ((const float4*)sU) + (size_t)w * 512;

    // Iterations t = 0..1022 do dots; the final h (reference discards the
    // last step's gates) is stored after the loop.
    for (int t = 0; t < T_STEPS - 1; t++) {
        // TOP store: hp_{t+1} from STALE state (needs no dots this step).
        if (owner) {
            float h_new = (1.0f - z_s) * h_s + z_s * ht_s;
            st_cg(&g_hp[(t + 1) & 3][myrow], h_new);
            h_s = h_new;
        }
        // One grid barrier per TWO steps (HBUF=4 covers anti-deps).
        if ((t & 1) == 0) gbar(e0 + (++ec), b);

        // This warp's K-quarter of hp_t (4 float4 per lane).
        const float4* hpq = ((const float4*)g_hp[t & 3]) + q * 128;
        float4 hp[4];
#pragma unroll
        for (int j = 0; j < 4; j++)
            hp[j] = __ldcg(hpq + l + 32 * j);

        float xzv = 0.f, xhv = 0.f;
        if (owner) {
            xzv = __ldg(&g_xz[(size_t)t * NHID + myrow]);
            xhv = __ldg(&g_xh[(size_t)t * NHID + myrow]);
        }

        // 4 partial dots over this K-quarter.
        float d0 = 0.f, d1 = 0.f, d2 = 0.f, d3 = 0.f;
#pragma unroll
        for (int j = 0; j < 4; j++) {
            float4 hv = hp[j];
            float4 a0 = uw[0 * 128 + l + 32 * j];
            d0 = fmaf(a0.x, hv.x, d0); d0 = fmaf(a0.y, hv.y, d0);
            d0 = fmaf(a0.z, hv.z, d0); d0 = fmaf(a0.w, hv.w, d0);
            float4 a1 = uw[1 * 128 + l + 32 * j];
            d1 = fmaf(a1.x, hv.x, d1); d1 = fmaf(a1.y, hv.y, d1);
            d1 = fmaf(a1.z, hv.z, d1); d1 = fmaf(a1.w, hv.w, d1);
            float4 a2 = uw[2 * 128 + l + 32 * j];
            d2 = fmaf(a2.x, hv.x, d2); d2 = fmaf(a2.y, hv.y, d2);
            d2 = fmaf(a2.z, hv.z, d2); d2 = fmaf(a2.w, hv.w, d2);
            float4 a3 = uw[3 * 128 + l + 32 * j];
            d3 = fmaf(a3.x, hv.x, d3); d3 = fmaf(a3.y, hv.y, d3);
            d3 = fmaf(a3.z, hv.z, d3); d3 = fmaf(a3.w, hv.w, d3);
        }
#pragma unroll
        for (int o = 16; o > 0; o >>= 1) {
            d0 += __shfl_xor_sync(0xffffffffu, d0, o);
            d1 += __shfl_xor_sync(0xffffffffu, d1, o);
            d2 += __shfl_xor_sync(0xffffffffu, d2, o);
            d3 += __shfl_xor_sync(0xffffffffu, d3, o);
        }

        // Exchange partials across the 4-warp group.
        if (l == 0) {
            float4 v; v.x = d0; v.y = d1; v.z = d2; v.w = d3;
            *(float4*)&sred4[t & 1][w][0] = v;
        }
        __syncthreads();

        if (owner) {
            // partial order: [dz(rp0), dh(rp0), dz(rp1), dh(rp1)]
            const int g4 = 4 * p;
            float dz = sred4[t & 1][g4 + 0][2 * l + 0] + sred4[t & 1][g4 + 1][2 * l + 0]
                     + sred4[t & 1][g4 + 2][2 * l + 0] + sred4[t & 1][g4 + 3][2 * l + 0];
            float dh = sred4[t & 1][g4 + 0][2 * l + 1] + sred4[t & 1][g4 + 1][2 * l + 1]
                     + sred4[t & 1][g4 + 2][2 * l + 1] + sred4[t & 1][g4 + 3][2 * l + 1];
            z_s  = 1.0f / (1.0f + expf(-(xzv + dz + bzr)));
            ht_s = tanhf(xhv + dh);
        }
    }

    // Final h = h_new_{1023} (last step's dots are dead).
    if (owner) {
        float h_new = (1.0f - z_s) * h_s + z_s * ht_s;
        st_cg(&g_hp[T_STEPS & 3][myrow], h_new);   // g_hp[0]
    }
    gbar(e0 + (++ec), b);

    // logits: warp gw = b*28 + w computes one category.
    {
        int gw = b * WARPS + w;
        if (gw < NCATS) {
            const float4* wo = (const float4*)(Wout + (size_t)gw * NHID);
            const float4* hf = (const float4*)(g_hp[0]);
            float s = 0.f;
#pragma unroll
            for (int j = 0; j < 16; j++) {
                float4 wv = __ldg(wo + l + 32 * j);
                float4 hv = __ldcg(hf + l + 32 * j);
                s = fmaf(wv.x, hv.x, s); s = fmaf(wv.y, hv.y, s);
                s = fmaf(wv.z, hv.z, s); s = fmaf(wv.w, hv.w, s);
            }
#pragma unroll
            for (int o = 16; o > 0; o >>= 1)
                s += __shfl_xor_sync(0xffffffffu, s, o);
            if (l == 0) g_logits[gw] = s;
        }
    }
    gbar(e0 + (++ec), b);

    // softmax over 1000 logits by block 0
    if (b == 0) {
        float m = -1e30f;
        for (int c = tid; c < NCATS; c += RTPB)
            m = fmaxf(m, __ldcg(&g_logits[c]));
#pragma unroll
        for (int o = 16; o > 0; o >>= 1)
            m = fmaxf(m, __shfl_xor_sync(0xffffffffu, m, o));
        if (l == 0) sredW[w] = m;
        __syncthreads();
        if (tid < 32) {
            float mm = (tid < WARPS) ? sredW[tid] : -1e30f;
#pragma unroll
            for (int o = 16; o > 0; o >>= 1)
                mm = fmaxf(mm, __shfl_xor_sync(0xffffffffu, mm, o));
            if (tid == 0) sredW[0] = mm;
        }
        __syncthreads();
        float gmax = sredW[0];
        __syncthreads();
        float s = 0.f;
        for (int c = tid; c < NCATS; c += RTPB)
            s += expf(__ldcg(&g_logits[c]) - gmax);
#pragma unroll
        for (int o = 16; o > 0; o >>= 1)
            s += __shfl_xor_sync(0xffffffffu, s, o);
        if (l == 0) sredW[w] = s;
        __syncthreads();
        if (tid < 32) {
            float ss = (tid < WARPS) ? sredW[tid] : 0.f;
#pragma unroll
            for (int o = 16; o > 0; o >>= 1)
                ss += __shfl_xor_sync(0xffffffffu, ss, o);
            if (tid == 0) sredW[0] = ss;
        }
        __syncthreads();
        float inv = 1.0f / sredW[0];
        for (int c = tid; c < NCATS; c += RTPB)
            out[c] = expf(__ldcg(&g_logits[c]) - gmax) * inv;
    }
}

// ---------------- launch ----------------
extern "C" void kernel_launch(void* const* d_in, const int* in_sizes, int n_in,
                              void* d_out, int out_size) {
    (void)in_sizes; (void)n_in; (void)out_size;
    const float* x    = (const float*)d_in[0];
    const float* Wh   = (const float*)d_in[1];
    const float* Wz   = (const float*)d_in[2];
    // d_in[3] = Wr : dead (rt never used)
    const float* Uh   = (const float*)d_in[4];
    const float* Uz   = (const float*)d_in[5];
    const float* bz   = (const float*)d_in[6];
    // d_in[7] = Ur, d_in[8] = br : dead
    const float* Wout = (const float*)d_in[9];
    // d_in[10] = h0 : dead (overwritten before first use)
    const float* zt0  = (const float*)d_in[11];
    const float* ht0  = (const float*)d_in[12];
    const float* hp0  = (const float*)d_in[13];
    float* out = (float*)d_out;

    const int smem = WARPS * 2048 * (int)sizeof(float);  // 229376 B
    cudaFuncSetAttribute(recur_kernel,
                         cudaFuncAttributeMaxDynamicSharedMemorySize, smem);

    dim3 ggrid(NHID / BN, T_STEPS / BM, 2);
    gemm_xw_kernel<<<ggrid, 256>>>(x, Wz, Wh);
    recur_kernel<<<GBLK, RTPB, smem>>>(Uz, Uh, bz, zt0, ht0, hp0, Wout, out);
}